// round 7
// baseline (speedup 1.0000x reference)
#include <cuda_runtime.h>

// YOLOV3TargetMerger: b=32, N=22743, M=50, C=80
// Inputs: 0 box_preds[b,N,4] 1 gt_boxes[b,M,4] 2 obj_t[b,N,1]
//         3 centers_t[b,N,2] 4 scales_t[b,N,2] 5 weights_t[b,N,2] 6 clas_t[b,N,80]
// Output (concat f32): obj[S], cen[2S], sca[2S], wei[2S], cls_t[80S], cls_m[80S]
//
// Single launch, block-specialized: first MAIN_BLOCKS CTAs do the per-anchor
// IOU/merge path; the rest stream the class targets/mask. The class stream is
// write-bandwidth bound (~466 MB of stores); main's work overlaps under it.

#define BATCH 32
#define MGT   50
#define NCLS  80
#define C4    (NCLS / 4)
#define THR   0.7f
#define EPSF  1e-12f

__global__ void __launch_bounds__(256) fused_specialized_kernel(
    const float4* __restrict__ bp,
    const float4* __restrict__ gt,
    const float*  __restrict__ obj,
    const float2* __restrict__ cen,
    const float2* __restrict__ sca,
    const float2* __restrict__ wei,
    const float4* __restrict__ cls,
    float* __restrict__ out,
    int N, long long S,
    int mainBlocks, int blocksPerBatch, long long total4)
{
    const int t = threadIdx.x;

    if (blockIdx.x >= mainBlocks) {
        // ---------------- class path (pure streaming, write-bound) ----------
        const long long idx =
            (long long)(blockIdx.x - mainBlocks) * blockDim.x + t;
        if (idx >= total4) return;

        const long long anchor = idx / C4;
        const bool mask = (obj[anchor] > 0.0f);

        float4 tv, mv;
        if (mask) {
            const float4 c = __ldcs(&cls[idx]);
            tv = c;
            mv.x = (c.x >= 0.0f) ? 1.0f : 0.0f;
            mv.y = (c.y >= 0.0f) ? 1.0f : 0.0f;
            mv.z = (c.z >= 0.0f) ? 1.0f : 0.0f;
            mv.w = (c.w >= 0.0f) ? 1.0f : 0.0f;
        } else {
            tv = make_float4(-1.0f, -1.0f, -1.0f, -1.0f);
            mv = make_float4(0.0f, 0.0f, 0.0f, 0.0f);
        }
        float4* out_t = (float4*)(out + 7LL  * S);
        float4* out_m = (float4*)(out + 87LL * S);
        __stcs(&out_t[idx], tv);
        __stcs(&out_m[idx], mv);
        return;
    }

    // ---------------- main path (IOU + obj/cen/sca/wei) ----------------
    __shared__ float4 sgt[MGT];
    __shared__ float  sarea[MGT];
    __shared__ int    scnt;

    const int b  = blockIdx.x / blocksPerBatch;
    const int nb = blockIdx.x % blocksPerBatch;

    // compact gt boxes: non-positive width/height => inter==0 vs every anchor,
    // which can never produce a hit (needs d>0, then 0 > 0.7*d is false).
    if (t == 0) scnt = 0;
    __syncthreads();
    if (t < MGT) {
        const float4 g = gt[b * MGT + t];
        if (g.z > g.x && g.w > g.y) {
            const int k = atomicAdd(&scnt, 1);
            sgt[k]   = g;
            sarea[k] = (g.z - g.x) * (g.w - g.y);
        }
    }
    __syncthreads();
    const int K = scnt;                       // ~12.5 expected

    const int n = nb * blockDim.x + t;
    if (n >= N) return;
    const long long i = (long long)b * N + n;

    const float o    = obj[i];
    const bool  mask = (o > 0.0f);

    float objout;
    if (mask) {
        objout = o;                           // IOU result unused -> skip loop
    } else {
        const float4 p = bp[i];
        const float area_p = (p.z - p.x) * (p.w - p.y);

        bool hit = false, ambig = false;
        for (int m = 0; m < K; m++) {
            const float4 g = sgt[m];
            const float w = fmaxf(fminf(p.z, g.z) - fmaxf(p.x, g.x), 0.0f);
            const float h = fmaxf(fminf(p.w, g.w) - fmaxf(p.y, g.y), 0.0f);
            const float inter = w * h;
            float u = area_p + sarea[m];
            u = u - inter;
            const float d = u + EPSF;         // ref denominator, same op order
            const float thr  = THR * d;
            const float diff = inter - thr;
            const float marg = 1e-6f * thr;
            const bool pos = (d > 0.0f);
            hit   = hit   | (pos & (diff >  marg));
            ambig = ambig | (pos & (fabsf(diff) <= marg));
        }
        if (ambig) {                          // rare: redo exactly (IEEE div)
            hit = false;
            for (int m = 0; m < K; m++) {
                const float4 g = sgt[m];
                const float w = fmaxf(fminf(p.z, g.z) - fmaxf(p.x, g.x), 0.0f);
                const float h = fmaxf(fminf(p.w, g.w) - fmaxf(p.y, g.y), 0.0f);
                const float inter = w * h;
                float u = area_p + sarea[m];
                u = u - inter;
                const float d = u + EPSF;
                hit = hit | ((inter / d) > THR);  // d<0 -> iou<=0 -> false (== ref)
            }
        }
        objout = hit ? -1.0f : 0.0f;
    }

    out[i] = objout;

    float2 c, s, w;
    if (mask) {
        c = cen[i]; s = sca[i]; w = wei[i];   // only read when used
    } else {
        c = s = w = make_float2(0.0f, 0.0f);
    }
    ((float2*)(out + S     ))[i] = c;
    ((float2*)(out + 3 * S ))[i] = s;
    ((float2*)(out + 5 * S ))[i] = w;
}

extern "C" void kernel_launch(void* const* d_in, const int* in_sizes, int n_in,
                              void* d_out, int out_size)
{
    const float4* bp  = (const float4*)d_in[0];
    const float4* gt  = (const float4*)d_in[1];
    const float*  obj = (const float*) d_in[2];
    const float2* cen = (const float2*)d_in[3];
    const float2* sca = (const float2*)d_in[4];
    const float2* wei = (const float2*)d_in[5];
    const float4* cls = (const float4*)d_in[6];

    const long long S = in_sizes[2];      // b * N
    const int N = (int)(S / BATCH);
    float* out = (float*)d_out;

    const int blocksPerBatch = (N + 255) / 256;
    const int mainBlocks = BATCH * blocksPerBatch;
    const long long total4 = S * C4;
    const long long classBlocks = (total4 + 255) / 256;
    const long long totalBlocks = mainBlocks + classBlocks;

    fused_specialized_kernel<<<(unsigned)totalBlocks, 256>>>(
        bp, gt, obj, cen, sca, wei, cls, out,
        N, S, mainBlocks, blocksPerBatch, total4);
}

// round 8
// speedup vs baseline: 1.0618x; 1.0618x over previous
#include <cuda_runtime.h>

// YOLOV3TargetMerger: b=32, N=22743, M=50, C=80
// Inputs: 0 box_preds[b,N,4] 1 gt_boxes[b,M,4] 2 obj_t[b,N,1]
//         3 centers_t[b,N,2] 4 scales_t[b,N,2] 5 weights_t[b,N,2] 6 clas_t[b,N,80]
// Output (concat f32): obj[S], cen[2S], sca[2S], wei[2S], cls_t[80S], cls_m[80S]

#define BATCH 32
#define MGT   50
#define NCLS  80
#define C4    (NCLS / 4)
#define THR   0.7f
#define EPSF  1e-12f
#define CLS_BLOCKS 2368      // 148 SMs * 16 CTAs
#define CLS_THREADS 256
#define UNROLL 4

__global__ void __launch_bounds__(256) merge_main_kernel(
    const float4* __restrict__ bp,
    const float4* __restrict__ gt,
    const float*  __restrict__ obj,
    const float2* __restrict__ cen,
    const float2* __restrict__ sca,
    const float2* __restrict__ wei,
    float* __restrict__ out,
    int N, long long S)
{
    __shared__ float4 sgt[MGT];
    __shared__ float  sarea[MGT];
    __shared__ int    scnt;

    const int b = blockIdx.y;
    const int t = threadIdx.x;

    // compact gt boxes: non-positive width/height => inter==0 vs every anchor,
    // which can never produce a hit (needs d>0, then 0 > 0.7*d is false).
    if (t == 0) scnt = 0;
    __syncthreads();
    if (t < MGT) {
        const float4 g = gt[b * MGT + t];
        if (g.z > g.x && g.w > g.y) {
            const int k = atomicAdd(&scnt, 1);
            sgt[k]   = g;
            sarea[k] = (g.z - g.x) * (g.w - g.y);
        }
    }
    __syncthreads();
    const int K = scnt;                       // ~12.5 expected

    const int n = blockIdx.x * blockDim.x + t;
    if (n >= N) return;
    const long long i = (long long)b * N + n;

    const float o    = obj[i];
    const bool  mask = (o > 0.0f);

    float objout;
    if (mask) {
        objout = o;                           // IOU result unused -> skip loop
    } else {
        const float4 p = bp[i];
        const float area_p = (p.z - p.x) * (p.w - p.y);

        bool hit = false, ambig = false;
        for (int m = 0; m < K; m++) {
            const float4 g = sgt[m];
            const float w = fmaxf(fminf(p.z, g.z) - fmaxf(p.x, g.x), 0.0f);
            const float h = fmaxf(fminf(p.w, g.w) - fmaxf(p.y, g.y), 0.0f);
            const float inter = w * h;
            float u = area_p + sarea[m];
            u = u - inter;
            const float d = u + EPSF;         // ref denominator, same op order
            const float thr  = THR * d;
            const float diff = inter - thr;
            const float marg = 1e-6f * thr;
            const bool pos = (d > 0.0f);
            hit   = hit   | (pos & (diff >  marg));
            ambig = ambig | (pos & (fabsf(diff) <= marg));
        }
        if (ambig) {                          // rare: redo exactly (IEEE div)
            hit = false;
            for (int m = 0; m < K; m++) {
                const float4 g = sgt[m];
                const float w = fmaxf(fminf(p.z, g.z) - fmaxf(p.x, g.x), 0.0f);
                const float h = fmaxf(fminf(p.w, g.w) - fmaxf(p.y, g.y), 0.0f);
                const float inter = w * h;
                float u = area_p + sarea[m];
                u = u - inter;
                const float d = u + EPSF;
                hit = hit | ((inter / d) > THR);  // d<0 -> iou<=0 -> false (== ref)
            }
        }
        objout = hit ? -1.0f : 0.0f;
    }

    out[i] = objout;

    float2 c, s, w;
    if (mask) {
        c = cen[i]; s = sca[i]; w = wei[i];   // only read when used
    } else {
        c = s = w = make_float2(0.0f, 0.0f);
    }
    ((float2*)(out + S     ))[i] = c;
    ((float2*)(out + 3 * S ))[i] = s;
    ((float2*)(out + 5 * S ))[i] = w;
}

// Grid-stride, 4-wide ILP batched: per loop body, 4 independent coalesced
// iterations (front-batched loads -> MLP>=4), predicated streaming cls loads.
__global__ void __launch_bounds__(CLS_THREADS) merge_class_kernel(
    const float*  __restrict__ obj,
    const float4* __restrict__ cls,
    float4* __restrict__ out_t,
    float4* __restrict__ out_m,
    long long total4)   // = S * C4
{
    const long long chunk  = (long long)CLS_THREADS * UNROLL;
    const long long stride = (long long)gridDim.x * chunk;
    long long base = (long long)blockIdx.x * chunk + threadIdx.x;

    for (; base < total4; base += stride) {
        long long idx[UNROLL];
        bool      ok[UNROLL];
        bool      mk[UNROLL];
#pragma unroll
        for (int j = 0; j < UNROLL; j++) {
            idx[j] = base + (long long)j * CLS_THREADS;
            ok[j]  = idx[j] < total4;
            mk[j]  = ok[j] && (obj[idx[j] / C4] > 0.0f);
        }
        float4 c[UNROLL];
#pragma unroll
        for (int j = 0; j < UNROLL; j++)
            c[j] = mk[j] ? __ldcs(&cls[idx[j]])
                         : make_float4(-1.0f, -1.0f, -1.0f, -1.0f);
#pragma unroll
        for (int j = 0; j < UNROLL; j++) {
            if (!ok[j]) continue;
            float4 mv;
            if (mk[j]) {
                mv.x = (c[j].x >= 0.0f) ? 1.0f : 0.0f;
                mv.y = (c[j].y >= 0.0f) ? 1.0f : 0.0f;
                mv.z = (c[j].z >= 0.0f) ? 1.0f : 0.0f;
                mv.w = (c[j].w >= 0.0f) ? 1.0f : 0.0f;
            } else {
                mv = make_float4(0.0f, 0.0f, 0.0f, 0.0f);
            }
            __stcs(&out_t[idx[j]], c[j]);
            __stcs(&out_m[idx[j]], mv);
        }
    }
}

extern "C" void kernel_launch(void* const* d_in, const int* in_sizes, int n_in,
                              void* d_out, int out_size)
{
    const float4* bp  = (const float4*)d_in[0];
    const float4* gt  = (const float4*)d_in[1];
    const float*  obj = (const float*) d_in[2];
    const float2* cen = (const float2*)d_in[3];
    const float2* sca = (const float2*)d_in[4];
    const float2* wei = (const float2*)d_in[5];
    const float*  cls = (const float*) d_in[6];

    const long long S = in_sizes[2];      // b * N
    const int N = (int)(S / BATCH);
    float* out = (float*)d_out;

    {
        dim3 block(256, 1, 1);
        dim3 grid((N + 255) / 256, BATCH, 1);
        merge_main_kernel<<<grid, block>>>(bp, gt, obj, cen, sca, wei, out, N, S);
    }
    {
        const long long total4 = S * C4;
        float4* out_t = (float4*)(out + 7LL  * S);
        float4* out_m = (float4*)(out + 87LL * S);
        merge_class_kernel<<<CLS_BLOCKS, CLS_THREADS>>>(obj, (const float4*)cls,
                                                        out_t, out_m, total4);
    }
}